// round 2
// baseline (speedup 1.0000x reference)
#include <cuda_runtime.h>
#include <math.h>

#define NN   50000
#define EE   800000
#define E2   (EE + NN)
#define FIN  256
#define HH   64
#define NHH  4
#define GDIM 256   // NH*H

// ---------------- device scratch (static, allowed) ----------------
__device__ int      g_flag;
__device__ int      g_src[EE];
__device__ int      g_dst[EE];
__device__ float    g_deg[NN];
__device__ float    g_dinv[NN];
__device__ float    g_t64[(size_t)NN * HH];
__device__ float    g_h[(size_t)NN * HH];
__device__ float    g_hp[(size_t)NN * GDIM];
__device__ float    g_gat[(size_t)NN * GDIM];
__device__ float    g_as[NN * NHH];
__device__ float    g_ad[NN * NHH];
__device__ unsigned g_amax[NN * NHH];
__device__ float    g_denom[NN * NHH];
__device__ float    g_alpha[(size_t)E2 * NHH];

__device__ __forceinline__ unsigned f_flip(float f) {
    unsigned u = __float_as_uint(f);
    return (u >> 31) ? ~u : (u | 0x80000000u);
}
__device__ __forceinline__ float f_unflip(unsigned u) {
    return (u & 0x80000000u) ? __uint_as_float(u & 0x7fffffffu)
                             : __uint_as_float(~u);
}

__global__ void k_detect(const int* __restrict__ ei32) {
    __shared__ int bad;
    if (threadIdx.x == 0) bad = 0;
    __syncthreads();
    for (int i = threadIdx.x; i < 4096; i += blockDim.x)
        if (ei32[2 * i + 1] != 0) bad = 1;
    __syncthreads();
    if (threadIdx.x == 0) g_flag = bad ? 0 : 1;
}

__global__ void k_convert(const int* __restrict__ p) {
    int i = blockIdx.x * blockDim.x + threadIdx.x;
    if (i >= EE) return;
    if (g_flag) {
        g_src[i] = p[2 * i];
        g_dst[i] = p[2 * (EE + i)];
    } else {
        g_src[i] = p[i];
        g_dst[i] = p[EE + i];
    }
}

__global__ void k_deg_init() {
    int i = blockIdx.x * blockDim.x + threadIdx.x;
    if (i < NN) g_deg[i] = 1.0f;
}
__global__ void k_deg_acc() {
    int i = blockIdx.x * blockDim.x + threadIdx.x;
    if (i < EE) atomicAdd(&g_deg[g_dst[i]], 1.0f);
}
__global__ void k_dinv() {
    int i = blockIdx.x * blockDim.x + threadIdx.x;
    if (i < NN) g_dinv[i] = rsqrtf(g_deg[i]);
}

template <int DIN, int DOUT, bool RELU, bool HASB>
__global__ __launch_bounds__(256) void k_gemm(const float* __restrict__ X,
                                              const float* __restrict__ W,
                                              const float* __restrict__ B,
                                              float* __restrict__ Y) {
    constexpr int NPB = 256 / DOUT;
    __shared__ float xs[NPB][DIN];
    int nloc = threadIdx.x / DOUT;
    int j    = threadIdx.x % DOUT;
    int n0   = blockIdx.x * NPB;
    for (int t = threadIdx.x; t < NPB * DIN; t += 256) {
        int r = t / DIN, c = t % DIN;
        int n = n0 + r;
        xs[r][c] = (n < NN) ? X[(size_t)n * DIN + c] : 0.f;
    }
    __syncthreads();
    int n = n0 + nloc;
    if (n >= NN) return;
    float acc = 0.f;
#pragma unroll 8
    for (int k = 0; k < DIN; k++)
        acc = fmaf(xs[nloc][k], W[k * DOUT + j], acc);
    if (HASB) acc += B[j];
    if (RELU) acc = fmaxf(acc, 0.f);
    Y[(size_t)n * DOUT + j] = acc;
}

__global__ void k_zero_h() {
    int i = blockIdx.x * blockDim.x + threadIdx.x;
    if (i < NN * HH) g_h[i] = 0.f;
}
__global__ void k_zero_gat() {
    int i = blockIdx.x * blockDim.x + threadIdx.x;
    if (i < NN * GDIM) g_gat[i] = 0.f;
}
__global__ void k_bias_relu(const float* __restrict__ b) {
    int i = blockIdx.x * blockDim.x + threadIdx.x;
    if (i < NN * HH) g_h[i] = fmaxf(g_h[i] + b[i % HH], 0.f);
}
__global__ void k_addbg(const float* __restrict__ bg) {
    int i = blockIdx.x * blockDim.x + threadIdx.x;
    if (i < NN * GDIM) g_gat[i] += bg[i & (GDIM - 1)];
}

__global__ void k_gcn_agg(const float* __restrict__ hin) {
    int w    = (blockIdx.x * blockDim.x + threadIdx.x) >> 5;
    int lane = threadIdx.x & 31;
    if (w >= E2) return;
    int s, d;
    if (w < EE) { s = g_src[w]; d = g_dst[w]; }
    else        { s = d = w - EE; }
    float norm = g_dinv[s] * g_dinv[d];
    float2 v = ((const float2*)(hin + (size_t)s * HH))[lane];
    float* o = g_h + (size_t)d * HH + 2 * lane;
    atomicAdd(o,     v.x * norm);
    atomicAdd(o + 1, v.y * norm);
}

__global__ void k_att(const float* __restrict__ att_src,
                      const float* __restrict__ att_dst) {
    int w    = (blockIdx.x * blockDim.x + threadIdx.x) >> 5;
    int lane = threadIdx.x & 31;
    if (w >= NN * NHH) return;
    int n = w >> 2, h = w & 3;
    float2 v  = ((const float2*)(g_hp + (size_t)n * GDIM + h * HH))[lane];
    float2 ws = ((const float2*)(att_src + h * HH))[lane];
    float2 wd = ((const float2*)(att_dst + h * HH))[lane];
    float ss = v.x * ws.x + v.y * ws.y;
    float sd = v.x * wd.x + v.y * wd.y;
    for (int o = 16; o; o >>= 1) {
        ss += __shfl_down_sync(0xffffffffu, ss, o);
        sd += __shfl_down_sync(0xffffffffu, sd, o);
    }
    if (lane == 0) { g_as[w] = ss; g_ad[w] = sd; }
}

__global__ void k_soft_init() {
    int i = blockIdx.x * blockDim.x + threadIdx.x;
    if (i < NN * NHH) {
        g_amax[i]  = f_flip(-INFINITY);
        g_denom[i] = 0.f;
    }
}

__global__ void k_alpha() {
    int i = blockIdx.x * blockDim.x + threadIdx.x;
    if (i >= E2 * NHH) return;
    int e = i >> 2, h = i & 3;
    int s, d;
    if (e < EE) { s = g_src[e]; d = g_dst[e]; }
    else        { s = d = e - EE; }
    float a = g_as[s * NHH + h] + g_ad[d * NHH + h];
    a = (a > 0.f) ? a : 0.2f * a;
    g_alpha[i] = a;
    atomicMax(&g_amax[d * NHH + h], f_flip(a));
}

__global__ void k_exp() {
    int i = blockIdx.x * blockDim.x + threadIdx.x;
    if (i >= E2 * NHH) return;
    int e = i >> 2, h = i & 3;
    int d = (e < EE) ? g_dst[e] : (e - EE);
    float m  = f_unflip(g_amax[d * NHH + h]);
    float ev = expf(g_alpha[i] - m);
    g_alpha[i] = ev;
    atomicAdd(&g_denom[d * NHH + h], ev);
}

__global__ void k_gat_agg() {
    int w    = (blockIdx.x * blockDim.x + threadIdx.x) >> 5;
    int lane = threadIdx.x & 31;
    if (w >= E2 * NHH) return;
    int e = w >> 2, h = w & 3;
    int s, d;
    if (e < EE) { s = g_src[e]; d = g_dst[e]; }
    else        { s = d = e - EE; }
    float coef = g_alpha[w] / g_denom[d * NHH + h];
    float2 v = ((const float2*)(g_hp + (size_t)s * GDIM + h * HH))[lane];
    float* o = g_gat + (size_t)d * GDIM + h * HH + 2 * lane;
    atomicAdd(o,     v.x * coef);
    atomicAdd(o + 1, v.y * coef);
}

__global__ void k_final(const float* __restrict__ wf2,
                        const float* __restrict__ bf2,
                        float* __restrict__ out) {
    int w    = (blockIdx.x * blockDim.x + threadIdx.x) >> 5;
    int lane = threadIdx.x & 31;
    if (w >= NN) return;
    float2 v  = ((const float2*)(g_t64 + (size_t)w * HH))[lane];
    float2 ww = ((const float2*)wf2)[lane];
    float s = v.x * ww.x + v.y * ww.y;
    for (int o = 16; o; o >>= 1) s += __shfl_down_sync(0xffffffffu, s, o);
    if (lane == 0) out[w] = s + bf2[0];
}

static inline int cdiv(long long a, int b) { return (int)((a + b - 1) / b); }

static float* sym_addr(const void* sym) {
    void* p = nullptr;
    cudaGetSymbolAddress(&p, sym);
    return (float*)p;
}

extern "C" void kernel_launch(void* const* d_in, const int* in_sizes, int n_in,
                              void* d_out, int out_size) {
    const float* x       = (const float*)d_in[0];
    const int*   ei      = (const int*)  d_in[1];
    const float* W1      = (const float*)d_in[2];
    const float* b1      = (const float*)d_in[3];
    const float* W2      = (const float*)d_in[4];
    const float* b2      = (const float*)d_in[5];
    const float* Wg      = (const float*)d_in[6];
    const float* att_src = (const float*)d_in[7];
    const float* att_dst = (const float*)d_in[8];
    const float* bg      = (const float*)d_in[9];
    const float* Wf1     = (const float*)d_in[10];
    const float* bf1     = (const float*)d_in[11];
    const float* Wf2     = (const float*)d_in[12];
    const float* bf2     = (const float*)d_in[13];
    float*       out     = (float*)d_out;

    static float* p_t64 = nullptr;
    static float* p_h   = nullptr;
    static float* p_hp  = nullptr;
    static float* p_gat = nullptr;
    if (!p_t64) {
        p_t64 = sym_addr(g_t64);
        p_h   = sym_addr(g_h);
        p_hp  = sym_addr(g_hp);
        p_gat = sym_addr(g_gat);
    }

    const int B = 256;

    // edge prep + degrees
    k_detect<<<1, B>>>(ei);
    k_convert<<<cdiv(EE, B), B>>>(ei);
    k_deg_init<<<cdiv(NN, B), B>>>();
    k_deg_acc<<<cdiv(EE, B), B>>>();
    k_dinv<<<cdiv(NN, B), B>>>();

    // GCN layer 1
    k_gemm<FIN, HH, false, false><<<cdiv(NN, 4), B>>>(x, W1, nullptr, p_t64);
    k_zero_h<<<cdiv(NN * HH, B), B>>>();
    k_gcn_agg<<<cdiv((long long)E2 * 32, B), B>>>(p_t64);
    k_bias_relu<<<cdiv(NN * HH, B), B>>>(b1);

    // GCN layer 2
    k_gemm<HH, HH, false, false><<<cdiv(NN, 4), B>>>(p_h, W2, nullptr, p_t64);
    k_zero_h<<<cdiv(NN * HH, B), B>>>();
    k_gcn_agg<<<cdiv((long long)E2 * 32, B), B>>>(p_t64);
    k_bias_relu<<<cdiv(NN * HH, B), B>>>(b2);

    // GAT
    k_gemm<HH, GDIM, false, false><<<NN, B>>>(p_h, Wg, nullptr, p_hp);
    k_att<<<cdiv((long long)NN * NHH * 32, B), B>>>(att_src, att_dst);
    k_soft_init<<<cdiv(NN * NHH, B), B>>>();
    k_alpha<<<cdiv((long long)E2 * NHH, B), B>>>();
    k_exp<<<cdiv((long long)E2 * NHH, B), B>>>();
    k_zero_gat<<<cdiv(NN * GDIM, B), B>>>();
    k_gat_agg<<<cdiv((long long)E2 * NHH * 32, B), B>>>();
    k_addbg<<<cdiv(NN * GDIM, B), B>>>(bg);

    // FF head
    k_gemm<GDIM, HH, true, true><<<cdiv(NN, 4), B>>>(p_gat, Wf1, bf1, p_t64);
    k_final<<<cdiv((long long)NN * 32, B), B>>>(Wf2, bf2, out);

    (void)in_sizes; (void)n_in; (void)out_size;
}

// round 3
// speedup vs baseline: 2.8215x; 2.8215x over previous
#include <cuda_runtime.h>
#include <math.h>

#define NN   50000
#define EE   800000
#define FIN  256
#define HH   64
#define NHH  4
#define GDIM 256   // NH*H
#define SCAN_B 196 // ceil(50000/256)

// ---------------- device scratch (static, allowed) ----------------
__device__ int      g_flag;
__device__ int      g_src[EE];
__device__ int      g_dst[EE];
__device__ int      g_cnt[NN];       // in-degree (excl self)
__device__ int      g_row[NN];       // CSR row offsets (exclusive scan of cnt)
__device__ int      g_cursor[NN];
__device__ int      g_bsum[SCAN_B];
__device__ int      g_csr[EE];       // src sorted by dst
__device__ float    g_dinv[NN];
__device__ float    g_t64[(size_t)NN * HH];
__device__ float    g_h[(size_t)NN * HH];
__device__ float    g_hp[(size_t)NN * GDIM];
__device__ float    g_gat[(size_t)NN * GDIM];
__device__ float    g_as[NN * NHH];
__device__ float    g_ad[NN * NHH];

// ---------------- edge prep ----------------
__global__ void k_detect(const int* __restrict__ ei32) {
    __shared__ int bad;
    if (threadIdx.x == 0) bad = 0;
    __syncthreads();
    for (int i = threadIdx.x; i < 4096; i += blockDim.x)
        if (ei32[2 * i + 1] != 0) bad = 1;
    __syncthreads();
    if (threadIdx.x == 0) g_flag = bad ? 0 : 1;
}

__global__ void k_zero_cnt() {
    int i = blockIdx.x * blockDim.x + threadIdx.x;
    if (i < NN) g_cnt[i] = 0;
}

// convert (int64 or int32) + histogram of dst
__global__ void k_convert(const int* __restrict__ p) {
    int i = blockIdx.x * blockDim.x + threadIdx.x;
    if (i >= EE) return;
    int s, d;
    if (g_flag) { s = p[2 * i]; d = p[2 * (EE + i)]; }
    else        { s = p[i];     d = p[EE + i]; }
    g_src[i] = s;
    g_dst[i] = d;
    atomicAdd(&g_cnt[d], 1);
}

// ---------------- 2-level exclusive scan of g_cnt ----------------
__global__ void k_scan1() {
    __shared__ int sm[256];
    int tid = threadIdx.x;
    int i = blockIdx.x * 256 + tid;
    int v = (i < NN) ? g_cnt[i] : 0;
    sm[tid] = v;
    __syncthreads();
    for (int o = 1; o < 256; o <<= 1) {
        int t = (tid >= o) ? sm[tid - o] : 0;
        __syncthreads();
        sm[tid] += t;
        __syncthreads();
    }
    if (i < NN) g_row[i] = sm[tid] - v;
    if (tid == 255) g_bsum[blockIdx.x] = sm[255];
}

__global__ void k_scan2() {
    __shared__ int sm[256];
    int tid = threadIdx.x;
    int v = (tid < SCAN_B) ? g_bsum[tid] : 0;
    sm[tid] = v;
    __syncthreads();
    for (int o = 1; o < 256; o <<= 1) {
        int t = (tid >= o) ? sm[tid - o] : 0;
        __syncthreads();
        sm[tid] += t;
        __syncthreads();
    }
    if (tid < SCAN_B) g_bsum[tid] = sm[tid] - v;
}

__global__ void k_scan3() {
    int i = blockIdx.x * blockDim.x + threadIdx.x;
    if (i >= NN) return;
    int r = g_row[i] + g_bsum[i >> 8];
    g_row[i] = r;
    g_cursor[i] = r;
    g_dinv[i] = rsqrtf((float)(g_cnt[i] + 1));  // +1 self-loop
}

__global__ void k_scatter() {
    int i = blockIdx.x * blockDim.x + threadIdx.x;
    if (i >= EE) return;
    int d = g_dst[i];
    int pos = atomicAdd(&g_cursor[d], 1);
    g_csr[pos] = g_src[i];
}

// ---------------- tiled GEMM: Y[N,DOUT] = X[N,DIN] @ W (+B)(ReLU) ----------
template <int DIN, int DOUT, bool RELU, bool HASB>
__global__ __launch_bounds__(256) void k_gemm2(const float* __restrict__ X,
                                               const float* __restrict__ W,
                                               const float* __restrict__ B,
                                               float* __restrict__ Y) {
    constexpr int NPB = 32;
    constexpr int TK  = 32;
    constexpr int G   = 256 / DOUT;   // thread groups over nodes
    constexpr int NT  = NPB / G;      // accumulators per thread
    __shared__ float xs[NPB][DIN];
    __shared__ float ws[TK][DOUT];
    int j  = threadIdx.x % DOUT;
    int g  = threadIdx.x / DOUT;
    int n0 = blockIdx.x * NPB;

    for (int t = threadIdx.x; t < NPB * DIN; t += 256) {
        int r = t / DIN, c = t % DIN;
        int n = n0 + r;
        xs[r][c] = (n < NN) ? X[(size_t)n * DIN + c] : 0.f;
    }
    float acc[NT];
#pragma unroll
    for (int t = 0; t < NT; t++) acc[t] = 0.f;

    for (int kt = 0; kt < DIN; kt += TK) {
        __syncthreads();
        for (int t = threadIdx.x; t < TK * DOUT; t += 256) {
            int r = t / DOUT, c = t % DOUT;
            ws[r][c] = W[(size_t)(kt + r) * DOUT + c];
        }
        __syncthreads();
#pragma unroll 8
        for (int k = 0; k < TK; k++) {
            float w = ws[k][j];
#pragma unroll
            for (int t = 0; t < NT; t++)
                acc[t] = fmaf(xs[t * G + g][kt + k], w, acc[t]);
        }
    }
#pragma unroll
    for (int t = 0; t < NT; t++) {
        int n = n0 + t * G + g;
        if (n < NN) {
            float v = acc[t];
            if (HASB) v += B[j];
            if (RELU) v = fmaxf(v, 0.f);
            Y[(size_t)n * DOUT + j] = v;
        }
    }
}

// ---------------- GCN aggregation (CSR, warp per node, fused bias+relu) ----
__global__ __launch_bounds__(256) void k_gcn_csr(const float* __restrict__ hin,
                                                 const float* __restrict__ b,
                                                 float* __restrict__ out) {
    int wid = threadIdx.x >> 5, lane = threadIdx.x & 31;
    int d = blockIdx.x * 8 + wid;
    if (d >= NN) return;
    int row0 = g_row[d];
    int row1 = row0 + g_cnt[d];
    float dd = g_dinv[d];
    float ax = 0.f, ay = 0.f;
    for (int base = row0; base < row1; base += 32) {
        int e = base + lane;
        int   sl = 0;
        float nl = 0.f;
        if (e < row1) { sl = g_csr[e]; nl = g_dinv[sl]; }
        int m = min(32, row1 - base);
        for (int i = 0; i < m; i++) {
            int   s    = __shfl_sync(0xffffffffu, sl, i);
            float norm = __shfl_sync(0xffffffffu, nl, i) * dd;
            float2 v = ((const float2*)(hin + (size_t)s * HH))[lane];
            ax = fmaf(v.x, norm, ax);
            ay = fmaf(v.y, norm, ay);
        }
    }
    // self loop
    {
        float2 v = ((const float2*)(hin + (size_t)d * HH))[lane];
        float n2 = dd * dd;
        ax = fmaf(v.x, n2, ax);
        ay = fmaf(v.y, n2, ay);
    }
    float2 bb = ((const float2*)b)[lane];
    float2 o;
    o.x = fmaxf(ax + bb.x, 0.f);
    o.y = fmaxf(ay + bb.y, 0.f);
    ((float2*)(out + (size_t)d * HH))[lane] = o;
}

// ---------------- GAT attention logits per node/head ----------------
__global__ void k_att(const float* __restrict__ att_src,
                      const float* __restrict__ att_dst) {
    int w    = (blockIdx.x * blockDim.x + threadIdx.x) >> 5;
    int lane = threadIdx.x & 31;
    if (w >= NN * NHH) return;
    int n = w >> 2, h = w & 3;
    float2 v  = ((const float2*)(g_hp + (size_t)n * GDIM + h * HH))[lane];
    float2 wsv = ((const float2*)(att_src + h * HH))[lane];
    float2 wdv = ((const float2*)(att_dst + h * HH))[lane];
    float ss = v.x * wsv.x + v.y * wsv.y;
    float sd = v.x * wdv.x + v.y * wdv.y;
    for (int o = 16; o; o >>= 1) {
        ss += __shfl_down_sync(0xffffffffu, ss, o);
        sd += __shfl_down_sync(0xffffffffu, sd, o);
    }
    if (lane == 0) { g_as[w] = ss; g_ad[w] = sd; }
}

__device__ __forceinline__ float lrelu(float a) {
    return a > 0.f ? a : 0.2f * a;
}
__device__ __forceinline__ float sel4(int h, float a, float b, float c, float d) {
    return h == 0 ? a : (h == 1 ? b : (h == 2 ? c : d));
}

// ---------------- fused GAT (CSR, warp per node): softmax + aggregation ----
__global__ __launch_bounds__(256) void k_gat_csr(const float* __restrict__ bg) {
    __shared__ int   ssm[8][32];
    __shared__ float wsm[8][32][4];
    int wid = threadIdx.x >> 5, lane = threadIdx.x & 31;
    int d = blockIdx.x * 8 + wid;
    if (d >= NN) return;
    int row0 = g_row[d];
    int row1 = row0 + g_cnt[d];
    int head = lane >> 3;

    float ad0 = g_ad[d * 4 + 0], ad1 = g_ad[d * 4 + 1];
    float ad2 = g_ad[d * 4 + 2], ad3 = g_ad[d * 4 + 3];

    // ---- pass 1: per-head max over row (incl self) ----
    float m0 = -INFINITY, m1 = -INFINITY, m2 = -INFINITY, m3 = -INFINITY;
    for (int e = row0 + lane; e < row1; e += 32) {
        int s = g_csr[e];
        const float* as = g_as + s * 4;
        m0 = fmaxf(m0, lrelu(as[0] + ad0));
        m1 = fmaxf(m1, lrelu(as[1] + ad1));
        m2 = fmaxf(m2, lrelu(as[2] + ad2));
        m3 = fmaxf(m3, lrelu(as[3] + ad3));
    }
    {   // self (idempotent across lanes)
        const float* as = g_as + d * 4;
        m0 = fmaxf(m0, lrelu(as[0] + ad0));
        m1 = fmaxf(m1, lrelu(as[1] + ad1));
        m2 = fmaxf(m2, lrelu(as[2] + ad2));
        m3 = fmaxf(m3, lrelu(as[3] + ad3));
    }
    for (int o = 16; o; o >>= 1) {
        m0 = fmaxf(m0, __shfl_xor_sync(0xffffffffu, m0, o));
        m1 = fmaxf(m1, __shfl_xor_sync(0xffffffffu, m1, o));
        m2 = fmaxf(m2, __shfl_xor_sync(0xffffffffu, m2, o));
        m3 = fmaxf(m3, __shfl_xor_sync(0xffffffffu, m3, o));
    }

    // ---- pass 2: exp weights (lane-parallel) + weighted feature gather ----
    float4 acc0 = make_float4(0.f, 0.f, 0.f, 0.f);
    float4 acc1 = make_float4(0.f, 0.f, 0.f, 0.f);
    float dn0 = 0.f, dn1 = 0.f, dn2 = 0.f, dn3 = 0.f;

    for (int base = row0; base < row1; base += 32) {
        int e = base + lane;
        float w0 = 0.f, w1 = 0.f, w2 = 0.f, w3 = 0.f;
        if (e < row1) {
            int s = g_csr[e];
            ssm[wid][lane] = s;
            const float* as = g_as + s * 4;
            w0 = __expf(lrelu(as[0] + ad0) - m0);
            w1 = __expf(lrelu(as[1] + ad1) - m1);
            w2 = __expf(lrelu(as[2] + ad2) - m2);
            w3 = __expf(lrelu(as[3] + ad3) - m3);
            wsm[wid][lane][0] = w0;
            wsm[wid][lane][1] = w1;
            wsm[wid][lane][2] = w2;
            wsm[wid][lane][3] = w3;
        }
        dn0 += w0; dn1 += w1; dn2 += w2; dn3 += w3;
        __syncwarp();
        int m = min(32, row1 - base);
        for (int i = 0; i < m; i++) {
            int   s = ssm[wid][i];
            float w = wsm[wid][i][head];
            const float4* hp4 = (const float4*)(g_hp + (size_t)s * GDIM);
            float4 v0 = hp4[2 * lane];
            float4 v1 = hp4[2 * lane + 1];
            acc0.x = fmaf(v0.x, w, acc0.x); acc0.y = fmaf(v0.y, w, acc0.y);
            acc0.z = fmaf(v0.z, w, acc0.z); acc0.w = fmaf(v0.w, w, acc0.w);
            acc1.x = fmaf(v1.x, w, acc1.x); acc1.y = fmaf(v1.y, w, acc1.y);
            acc1.z = fmaf(v1.z, w, acc1.z); acc1.w = fmaf(v1.w, w, acc1.w);
        }
        __syncwarp();
    }
    // reduce denominators across lanes (each lane owned distinct edges)
    for (int o = 16; o; o >>= 1) {
        dn0 += __shfl_xor_sync(0xffffffffu, dn0, o);
        dn1 += __shfl_xor_sync(0xffffffffu, dn1, o);
        dn2 += __shfl_xor_sync(0xffffffffu, dn2, o);
        dn3 += __shfl_xor_sync(0xffffffffu, dn3, o);
    }
    float mh  = sel4(head, m0, m1, m2, m3);
    float adh = sel4(head, ad0, ad1, ad2, ad3);
    float dnh = sel4(head, dn0, dn1, dn2, dn3);

    // self loop contribution
    float wslf = __expf(lrelu(g_as[d * 4 + head] + adh) - mh);
    dnh += wslf;
    {
        const float4* hp4 = (const float4*)(g_hp + (size_t)d * GDIM);
        float4 v0 = hp4[2 * lane];
        float4 v1 = hp4[2 * lane + 1];
        acc0.x = fmaf(v0.x, wslf, acc0.x); acc0.y = fmaf(v0.y, wslf, acc0.y);
        acc0.z = fmaf(v0.z, wslf, acc0.z); acc0.w = fmaf(v0.w, wslf, acc0.w);
        acc1.x = fmaf(v1.x, wslf, acc1.x); acc1.y = fmaf(v1.y, wslf, acc1.y);
        acc1.z = fmaf(v1.z, wslf, acc1.z); acc1.w = fmaf(v1.w, wslf, acc1.w);
    }
    float inv = 1.f / dnh;
    const float4* bg4 = (const float4*)bg;
    float4 b0 = bg4[2 * lane], b1 = bg4[2 * lane + 1];
    float4 o0, o1;
    o0.x = acc0.x * inv + b0.x; o0.y = acc0.y * inv + b0.y;
    o0.z = acc0.z * inv + b0.z; o0.w = acc0.w * inv + b0.w;
    o1.x = acc1.x * inv + b1.x; o1.y = acc1.y * inv + b1.y;
    o1.z = acc1.z * inv + b1.z; o1.w = acc1.w * inv + b1.w;
    float4* out4 = (float4*)(g_gat + (size_t)d * GDIM);
    out4[2 * lane]     = o0;
    out4[2 * lane + 1] = o1;
}

// ---------------- final projection ----------------
__global__ void k_final(const float* __restrict__ wf2,
                        const float* __restrict__ bf2,
                        float* __restrict__ out) {
    int w    = (blockIdx.x * blockDim.x + threadIdx.x) >> 5;
    int lane = threadIdx.x & 31;
    if (w >= NN) return;
    float2 v  = ((const float2*)(g_t64 + (size_t)w * HH))[lane];
    float2 ww = ((const float2*)wf2)[lane];
    float s = v.x * ww.x + v.y * ww.y;
    for (int o = 16; o; o >>= 1) s += __shfl_down_sync(0xffffffffu, s, o);
    if (lane == 0) out[w] = s + bf2[0];
}

static inline int cdiv(long long a, int b) { return (int)((a + b - 1) / b); }

static float* sym_addr(const void* sym) {
    void* p = nullptr;
    cudaGetSymbolAddress(&p, sym);
    return (float*)p;
}

extern "C" void kernel_launch(void* const* d_in, const int* in_sizes, int n_in,
                              void* d_out, int out_size) {
    const float* x       = (const float*)d_in[0];
    const int*   ei      = (const int*)  d_in[1];
    const float* W1      = (const float*)d_in[2];
    const float* b1      = (const float*)d_in[3];
    const float* W2      = (const float*)d_in[4];
    const float* b2      = (const float*)d_in[5];
    const float* Wg      = (const float*)d_in[6];
    const float* att_src = (const float*)d_in[7];
    const float* att_dst = (const float*)d_in[8];
    const float* bg      = (const float*)d_in[9];
    const float* Wf1     = (const float*)d_in[10];
    const float* bf1     = (const float*)d_in[11];
    const float* Wf2     = (const float*)d_in[12];
    const float* bf2     = (const float*)d_in[13];
    float*       out     = (float*)d_out;

    static float* p_t64 = nullptr;
    static float* p_h   = nullptr;
    static float* p_hp  = nullptr;
    static float* p_gat = nullptr;
    if (!p_t64) {
        p_t64 = sym_addr(g_t64);
        p_h   = sym_addr(g_h);
        p_hp  = sym_addr(g_hp);
        p_gat = sym_addr(g_gat);
    }

    const int B = 256;

    // ---- CSR build ----
    k_detect<<<1, B>>>(ei);
    k_zero_cnt<<<cdiv(NN, B), B>>>();
    k_convert<<<cdiv(EE, B), B>>>(ei);
    k_scan1<<<SCAN_B, B>>>();
    k_scan2<<<1, B>>>();
    k_scan3<<<cdiv(NN, B), B>>>();
    k_scatter<<<cdiv(EE, B), B>>>();

    // ---- GCN layer 1: h = relu(agg(x@W1) + b1) ----
    k_gemm2<FIN, HH, false, false><<<cdiv(NN, 32), B>>>(x, W1, nullptr, p_t64);
    k_gcn_csr<<<cdiv(NN, 8), B>>>(p_t64, b1, p_h);

    // ---- GCN layer 2 ----
    k_gemm2<HH, HH, false, false><<<cdiv(NN, 32), B>>>(p_h, W2, nullptr, p_t64);
    k_gcn_csr<<<cdiv(NN, 8), B>>>(p_t64, b2, p_h);

    // ---- GAT ----
    k_gemm2<HH, GDIM, false, false><<<cdiv(NN, 32), B>>>(p_h, Wg, nullptr, p_hp);
    k_att<<<cdiv((long long)NN * NHH * 32, B), B>>>(att_src, att_dst);
    k_gat_csr<<<cdiv(NN, 8), B>>>(bg);

    // ---- FF head ----
    k_gemm2<GDIM, HH, true, true><<<cdiv(NN, 32), B>>>(p_gat, Wf1, bf1, p_t64);
    k_final<<<cdiv((long long)NN * 32, B), B>>>(Wf2, bf2, out);

    (void)in_sizes; (void)n_in; (void)out_size;
}

// round 6
// speedup vs baseline: 3.3497x; 1.1872x over previous
#include <cuda_runtime.h>
#include <cuda_fp16.h>
#include <math.h>

#define NN   50000
#define EE   800000
#define FIN  256
#define HH   64
#define NHH  4
#define GDIM 256   // NH*H
#define SCAN_B 196 // ceil(50000/256)

// ---------------- device scratch (static, allowed) ----------------
__device__ int      g_flag;
__device__ int      g_src[EE];
__device__ int      g_dst[EE];
__device__ int      g_cnt[NN];
__device__ int      g_row[NN];
__device__ int      g_cursor[NN];
__device__ int      g_bsum[SCAN_B];
__device__ int      g_csr[EE];
__device__ float    g_wn[EE];        // dinv[src] per CSR slot
__device__ float    g_dinv[NN];
__device__ float    g_t64[(size_t)NN * HH];
__device__ float    g_h[(size_t)NN * HH];
__device__ __align__(16) __half g_hph[(size_t)NN * GDIM];
__device__ float    g_gat[(size_t)NN * GDIM];
__device__ float    g_as[NN * NHH];
__device__ float    g_ad[NN * NHH];

// ---------------- edge prep ----------------
__global__ void k_prep(const int* __restrict__ ei32) {
    int i = blockIdx.x * 256 + threadIdx.x;
    if (i < NN) g_cnt[i] = 0;
    if (blockIdx.x == 0) {
        __shared__ int bad;
        if (threadIdx.x == 0) bad = 0;
        __syncthreads();
        for (int t = threadIdx.x; t < 4096; t += 256)
            if (ei32[2 * t + 1] != 0) bad = 1;
        __syncthreads();
        if (threadIdx.x == 0) g_flag = bad ? 0 : 1;
    }
}

__global__ void k_convert(const int* __restrict__ p) {
    int i = blockIdx.x * blockDim.x + threadIdx.x;
    if (i >= EE) return;
    int s, d;
    if (g_flag) { s = p[2 * i]; d = p[2 * (EE + i)]; }
    else        { s = p[i];     d = p[EE + i]; }
    g_src[i] = s;
    g_dst[i] = d;
    atomicAdd(&g_cnt[d], 1);
}

// ---------------- 2-level exclusive scan of g_cnt ----------------
__global__ void k_scan1() {
    __shared__ int sm[256];
    int tid = threadIdx.x;
    int i = blockIdx.x * 256 + tid;
    int v = (i < NN) ? g_cnt[i] : 0;
    sm[tid] = v;
    __syncthreads();
    for (int o = 1; o < 256; o <<= 1) {
        int t = (tid >= o) ? sm[tid - o] : 0;
        __syncthreads();
        sm[tid] += t;
        __syncthreads();
    }
    if (i < NN) g_row[i] = sm[tid] - v;
    if (tid == 255) g_bsum[blockIdx.x] = sm[255];
}

__global__ void k_scan2() {
    __shared__ int sm[256];
    int tid = threadIdx.x;
    int v = (tid < SCAN_B) ? g_bsum[tid] : 0;
    sm[tid] = v;
    __syncthreads();
    for (int o = 1; o < 256; o <<= 1) {
        int t = (tid >= o) ? sm[tid - o] : 0;
        __syncthreads();
        sm[tid] += t;
        __syncthreads();
    }
    if (tid < SCAN_B) g_bsum[tid] = sm[tid] - v;
}

__global__ void k_scan3() {
    int i = blockIdx.x * blockDim.x + threadIdx.x;
    if (i >= NN) return;
    int r = g_row[i] + g_bsum[i >> 8];
    g_row[i] = r;
    g_cursor[i] = r;
    g_dinv[i] = rsqrtf((float)(g_cnt[i] + 1));
}

__global__ void k_scatter() {
    int i = blockIdx.x * blockDim.x + threadIdx.x;
    if (i >= EE) return;
    int d = g_dst[i];
    int s = g_src[i];
    int pos = atomicAdd(&g_cursor[d], 1);
    g_csr[pos] = s;
    g_wn[pos]  = g_dinv[s];
}

// ---------------- GEMM (DOUT=64): Y = X @ W, 2D register tile ----------
template <int DIN>
__global__ __launch_bounds__(256) void k_gemm_n64(const float* __restrict__ X,
                                                  const float* __restrict__ W,
                                                  float* __restrict__ Y) {
    __shared__ float xs[32][DIN + 1];
    __shared__ float ws[32][64];
    int jg = threadIdx.x & 15;
    int tg = threadIdx.x >> 4;
    int n0 = blockIdx.x * 32;
    for (int t = threadIdx.x; t < 32 * DIN; t += 256) {
        int r = t / DIN, c = t % DIN;
        int n = n0 + r;
        xs[r][c] = (n < NN) ? X[(size_t)n * DIN + c] : 0.f;
    }
    float acc[2][4] = {};
    for (int kt = 0; kt < DIN; kt += 32) {
        __syncthreads();
        for (int t = threadIdx.x; t < 32 * 64; t += 256) {
            int r = t >> 6, c = t & 63;
            ws[r][c] = W[(size_t)(kt + r) * 64 + c];
        }
        __syncthreads();
#pragma unroll
        for (int k = 0; k < 32; k++) {
            float4 w4 = *(const float4*)&ws[k][jg * 4];
#pragma unroll
            for (int tt = 0; tt < 2; tt++) {
                float xv = xs[tg * 2 + tt][kt + k];
                acc[tt][0] = fmaf(xv, w4.x, acc[tt][0]);
                acc[tt][1] = fmaf(xv, w4.y, acc[tt][1]);
                acc[tt][2] = fmaf(xv, w4.z, acc[tt][2]);
                acc[tt][3] = fmaf(xv, w4.w, acc[tt][3]);
            }
        }
    }
#pragma unroll
    for (int tt = 0; tt < 2; tt++) {
        int n = n0 + tg * 2 + tt;
        if (n < NN)
            *(float4*)&Y[(size_t)n * 64 + jg * 4] =
                make_float4(acc[tt][0], acc[tt][1], acc[tt][2], acc[tt][3]);
    }
}

// ---------------- Wg GEMM (64->256) + att epilogue + fp16 store ----------
__global__ __launch_bounds__(256) void k_gemm_gat(const float* __restrict__ X,
                                                  const float* __restrict__ W,
                                                  const float* __restrict__ att_src,
                                                  const float* __restrict__ att_dst) {
    __shared__ float xs[32][64];
    __shared__ float ws[16][256];
    int jg = threadIdx.x & 63;
    int tg = threadIdx.x >> 6;
    int lane = threadIdx.x & 31;
    int n0 = blockIdx.x * 32;
    for (int t = threadIdx.x; t < 32 * 64; t += 256) {
        int r = t >> 6, c = t & 63;
        int n = n0 + r;
        xs[r][c] = (n < NN) ? X[(size_t)n * 64 + c] : 0.f;
    }
    float acc[8][4] = {};
    for (int kt = 0; kt < 64; kt += 16) {
        __syncthreads();
        for (int t = threadIdx.x; t < 16 * 256; t += 256) {
            int r = t >> 8, c = t & 255;
            ws[r][c] = W[(size_t)(kt + r) * 256 + c];
        }
        __syncthreads();
#pragma unroll
        for (int k = 0; k < 16; k++) {
            float4 w4 = *(const float4*)&ws[k][jg * 4];
#pragma unroll
            for (int tt = 0; tt < 8; tt++) {
                float xv = xs[tg * 8 + tt][kt + k];
                acc[tt][0] = fmaf(xv, w4.x, acc[tt][0]);
                acc[tt][1] = fmaf(xv, w4.y, acc[tt][1]);
                acc[tt][2] = fmaf(xv, w4.z, acc[tt][2]);
                acc[tt][3] = fmaf(xv, w4.w, acc[tt][3]);
            }
        }
    }
    // ---- attention-logit epilogue (exact fp32) ----
    int j0 = jg * 4;
    int head = jg >> 4;          // 16 jg groups (64 cols) per head
    float4 asw = *(const float4*)&att_src[j0];
    float4 adw = *(const float4*)&att_dst[j0];
#pragma unroll
    for (int tt = 0; tt < 8; tt++) {
        float vs = acc[tt][0] * asw.x + acc[tt][1] * asw.y +
                   acc[tt][2] * asw.z + acc[tt][3] * asw.w;
        float vd = acc[tt][0] * adw.x + acc[tt][1] * adw.y +
                   acc[tt][2] * adw.z + acc[tt][3] * adw.w;
        for (int o = 8; o; o >>= 1) {       // reduce within 16-lane head group
            vs += __shfl_xor_sync(0xffffffffu, vs, o);
            vd += __shfl_xor_sync(0xffffffffu, vd, o);
        }
        if ((lane & 15) == 0) {
            int n = n0 + tg * 8 + tt;
            if (n < NN) {
                g_as[n * 4 + head] = vs;
                g_ad[n * 4 + head] = vd;
            }
        }
    }
    // ---- fp16 hp store ----
#pragma unroll
    for (int tt = 0; tt < 8; tt++) {
        int n = n0 + tg * 8 + tt;
        if (n < NN) {
            union { __half2 h2[2]; uint2 u; } pk;
            pk.h2[0] = __floats2half2_rn(acc[tt][0], acc[tt][1]);
            pk.h2[1] = __floats2half2_rn(acc[tt][2], acc[tt][3]);
            *(uint2*)(g_hph + (size_t)n * GDIM + j0) = pk.u;
        }
    }
}

// ---------------- head GEMM (256->64) + relu + Wf2 dot -> out ------------
__global__ __launch_bounds__(256) void k_gemm_head(const float* __restrict__ X,
                                                   const float* __restrict__ W,
                                                   const float* __restrict__ bf1,
                                                   const float* __restrict__ wf2,
                                                   const float* __restrict__ bf2,
                                                   float* __restrict__ out) {
    __shared__ float xs[32][257];
    __shared__ float ws[32][64];
    int jg = threadIdx.x & 15;
    int tg = threadIdx.x >> 4;
    int lane = threadIdx.x & 31;
    int n0 = blockIdx.x * 32;
    for (int t = threadIdx.x; t < 32 * 256; t += 256) {
        int r = t >> 8, c = t & 255;
        int n = n0 + r;
        xs[r][c] = (n < NN) ? X[(size_t)n * 256 + c] : 0.f;
    }
    float acc[2][4] = {};
    for (int kt = 0; kt < 256; kt += 32) {
        __syncthreads();
        for (int t = threadIdx.x; t < 32 * 64; t += 256) {
            int r = t >> 6, c = t & 63;
            ws[r][c] = W[(size_t)(kt + r) * 64 + c];
        }
        __syncthreads();
#pragma unroll
        for (int k = 0; k < 32; k++) {
            float4 w4 = *(const float4*)&ws[k][jg * 4];
#pragma unroll
            for (int tt = 0; tt < 2; tt++) {
                float xv = xs[tg * 2 + tt][kt + k];
                acc[tt][0] = fmaf(xv, w4.x, acc[tt][0]);
                acc[tt][1] = fmaf(xv, w4.y, acc[tt][1]);
                acc[tt][2] = fmaf(xv, w4.z, acc[tt][2]);
                acc[tt][3] = fmaf(xv, w4.w, acc[tt][3]);
            }
        }
    }
    int j0 = jg * 4;
    float4 b4 = *(const float4*)&bf1[j0];
    float4 w2 = *(const float4*)&wf2[j0];
#pragma unroll
    for (int tt = 0; tt < 2; tt++) {
        float v = fmaxf(acc[tt][0] + b4.x, 0.f) * w2.x +
                  fmaxf(acc[tt][1] + b4.y, 0.f) * w2.y +
                  fmaxf(acc[tt][2] + b4.z, 0.f) * w2.z +
                  fmaxf(acc[tt][3] + b4.w, 0.f) * w2.w;
        for (int o = 8; o; o >>= 1)
            v += __shfl_xor_sync(0xffffffffu, v, o);
        if ((lane & 15) == 0) {
            int n = n0 + tg * 2 + tt;
            if (n < NN) out[n] = v + bf2[0];
        }
    }
}

// ---------------- GCN aggregation (CSR, warp per node) -------------------
__global__ __launch_bounds__(256) void k_gcn_csr(const float* __restrict__ hin,
                                                 const float* __restrict__ b,
                                                 float* __restrict__ out) {
    int wid = threadIdx.x >> 5, lane = threadIdx.x & 31;
    int d = blockIdx.x * 8 + wid;
    if (d >= NN) return;
    int row0 = g_row[d];
    int row1 = row0 + g_cnt[d];
    float dd = g_dinv[d];
    float ax = 0.f, ay = 0.f;
    for (int base = row0; base < row1; base += 32) {
        int e = base + lane;
        int   sl = 0;
        float nl = 0.f;
        if (e < row1) { sl = g_csr[e]; nl = g_wn[e]; }
        int m = min(32, row1 - base);
        for (int i = 0; i < m; i++) {
            int   s    = __shfl_sync(0xffffffffu, sl, i);
            float norm = __shfl_sync(0xffffffffu, nl, i) * dd;
            float2 v = ((const float2*)(hin + (size_t)s * HH))[lane];
            ax = fmaf(v.x, norm, ax);
            ay = fmaf(v.y, norm, ay);
        }
    }
    {   // self loop
        float2 v = ((const float2*)(hin + (size_t)d * HH))[lane];
        float n2 = dd * dd;
        ax = fmaf(v.x, n2, ax);
        ay = fmaf(v.y, n2, ay);
    }
    float2 bb = ((const float2*)b)[lane];
    float2 o;
    o.x = fmaxf(ax + bb.x, 0.f);
    o.y = fmaxf(ay + bb.y, 0.f);
    ((float2*)(out + (size_t)d * HH))[lane] = o;
}

__device__ __forceinline__ float lrelu(float a) {
    return a > 0.f ? a : 0.2f * a;
}
__device__ __forceinline__ float sel4(int h, float a, float b, float c, float d) {
    return h == 0 ? a : (h == 1 ? b : (h == 2 ? c : d));
}

// ---------------- fused GAT (CSR, warp per node, fp16 gather) -------------
__global__ __launch_bounds__(256) void k_gat_csr(const float* __restrict__ bg,
                                                 float* __restrict__ outg) {
    __shared__ int   ssm[8][32];
    __shared__ float wsm[8][32][4];
    int wid = threadIdx.x >> 5, lane = threadIdx.x & 31;
    int d = blockIdx.x * 8 + wid;
    if (d >= NN) return;
    int row0 = g_row[d];
    int row1 = row0 + g_cnt[d];
    int head = lane >> 3;               // 8 dims/lane -> 8 lanes/head

    float ad0 = g_ad[d * 4 + 0], ad1 = g_ad[d * 4 + 1];
    float ad2 = g_ad[d * 4 + 2], ad3 = g_ad[d * 4 + 3];

    // ---- pass 1: per-head max (incl self) ----
    float m0 = -INFINITY, m1 = -INFINITY, m2 = -INFINITY, m3 = -INFINITY;
    for (int e = row0 + lane; e < row1; e += 32) {
        int s = g_csr[e];
        const float* as = g_as + s * 4;
        m0 = fmaxf(m0, lrelu(as[0] + ad0));
        m1 = fmaxf(m1, lrelu(as[1] + ad1));
        m2 = fmaxf(m2, lrelu(as[2] + ad2));
        m3 = fmaxf(m3, lrelu(as[3] + ad3));
    }
    {
        const float* as = g_as + d * 4;
        m0 = fmaxf(m0, lrelu(as[0] + ad0));
        m1 = fmaxf(m1, lrelu(as[1] + ad1));
        m2 = fmaxf(m2, lrelu(as[2] + ad2));
        m3 = fmaxf(m3, lrelu(as[3] + ad3));
    }
    for (int o = 16; o; o >>= 1) {
        m0 = fmaxf(m0, __shfl_xor_sync(0xffffffffu, m0, o));
        m1 = fmaxf(m1, __shfl_xor_sync(0xffffffffu, m1, o));
        m2 = fmaxf(m2, __shfl_xor_sync(0xffffffffu, m2, o));
        m3 = fmaxf(m3, __shfl_xor_sync(0xffffffffu, m3, o));
    }

    // ---- pass 2: exp weights + weighted fp16 gather ----
    float a0 = 0.f, a1 = 0.f, a2 = 0.f, a3 = 0.f;
    float a4 = 0.f, a5 = 0.f, a6 = 0.f, a7 = 0.f;
    float dn0 = 0.f, dn1 = 0.f, dn2 = 0.f, dn3 = 0.f;

    for (int base = row0; base < row1; base += 32) {
        int e = base + lane;
        float w0 = 0.f, w1 = 0.f, w2 = 0.f, w3 = 0.f;
        if (e < row1) {
            int s = g_csr[e];
            ssm[wid][lane] = s;
            const float* as = g_as + s * 4;
            w0 = __expf(lrelu(as[0] + ad0) - m0);
            w1 = __expf(lrelu(as[1] + ad1) - m1);
            w2 = __expf(lrelu(as[2] + ad2) - m2);
            w3 = __expf(lrelu(as[3] + ad3) - m3);
            wsm[wid][lane][0] = w0;
            wsm[wid][lane][1] = w1;
            wsm[wid][lane][2] = w2;
            wsm[wid][lane][3] = w3;
        }
        dn0 += w0; dn1 += w1; dn2 += w2; dn3 += w3;
        __syncwarp();
        int m = min(32, row1 - base);
        for (int i = 0; i < m; i++) {
            int   s  = ssm[wid][i];
            float wt = wsm[wid][i][head];
            uint4 p = *(const uint4*)(g_hph + (size_t)s * GDIM + lane * 8);
            float2 f0 = __half22float2(*(__half2*)&p.x);
            float2 f1 = __half22float2(*(__half2*)&p.y);
            float2 f2 = __half22float2(*(__half2*)&p.z);
            float2 f3 = __half22float2(*(__half2*)&p.w);
            a0 = fmaf(f0.x, wt, a0); a1 = fmaf(f0.y, wt, a1);
            a2 = fmaf(f1.x, wt, a2); a3 = fmaf(f1.y, wt, a3);
            a4 = fmaf(f2.x, wt, a4); a5 = fmaf(f2.y, wt, a5);
            a6 = fmaf(f3.x, wt, a6); a7 = fmaf(f3.y, wt, a7);
        }
        __syncwarp();
    }
    for (int o = 16; o; o >>= 1) {
        dn0 += __shfl_xor_sync(0xffffffffu, dn0, o);
        dn1 += __shfl_xor_sync(0xffffffffu, dn1, o);
        dn2 += __shfl_xor_sync(0xffffffffu, dn2, o);
        dn3 += __shfl_xor_sync(0xffffffffu, dn3, o);
    }
    float mh  = sel4(head, m0, m1, m2, m3);
    float adh = sel4(head, ad0, ad1, ad2, ad3);
    float dnh = sel4(head, dn0, dn1, dn2, dn3);

    // self loop
    float wslf = __expf(lrelu(g_as[d * 4 + head] + adh) - mh);
    dnh += wslf;
    {
        uint4 p = *(const uint4*)(g_hph + (size_t)d * GDIM + lane * 8);
        float2 f0 = __half22float2(*(__half2*)&p.x);
        float2 f1 = __half22float2(*(__half2*)&p.y);
        float2 f2 = __half22float2(*(__half2*)&p.z);
        float2 f3 = __half22float2(*(__half2*)&p.w);
        a0 = fmaf(f0.x, wslf, a0); a1 = fmaf(f0.y, wslf, a1);
        a2 = fmaf(f1.x, wslf, a2); a3 = fmaf(f1.y, wslf, a3);
        a4 = fmaf(f2.x, wslf, a4); a5 = fmaf(f2.y, wslf, a5);
        a6 = fmaf(f3.x, wslf, a6); a7 = fmaf(f3.y, wslf, a7);
    }
    float inv = 1.f / dnh;
    const float4* bg4 = (const float4*)(bg + lane * 8);
    float4 b0 = bg4[0], b1 = bg4[1];
    float4 o0 = make_float4(a0 * inv + b0.x, a1 * inv + b0.y,
                            a2 * inv + b0.z, a3 * inv + b0.w);
    float4 o1 = make_float4(a4 * inv + b1.x, a5 * inv + b1.y,
                            a6 * inv + b1.z, a7 * inv + b1.w);
    float4* out4 = (float4*)(outg + (size_t)d * GDIM + lane * 8);
    out4[0] = o0;
    out4[1] = o1;
}

static inline int cdiv(long long a, int b) { return (int)((a + b - 1) / b); }

static float* sym_addr(const void* sym) {
    void* p = nullptr;
    cudaGetSymbolAddress(&p, sym);
    return (float*)p;
}

extern "C" void kernel_launch(void* const* d_in, const int* in_sizes, int n_in,
                              void* d_out, int out_size) {
    const float* x       = (const float*)d_in[0];
    const int*   ei      = (const int*)  d_in[1];
    const float* W1      = (const float*)d_in[2];
    const float* b1      = (const float*)d_in[3];
    const float* W2      = (const float*)d_in[4];
    const float* b2      = (const float*)d_in[5];
    const float* Wg      = (const float*)d_in[6];
    const float* att_src = (const float*)d_in[7];
    const float* att_dst = (const float*)d_in[8];
    const float* bg      = (const float*)d_in[9];
    const float* Wf1     = (const float*)d_in[10];
    const float* bf1     = (const float*)d_in[11];
    const float* Wf2     = (const float*)d_in[12];
    const float* bf2     = (const float*)d_in[13];
    float*       out     = (float*)d_out;

    static float* p_t64 = nullptr;
    static float* p_h   = nullptr;
    static float* p_gat = nullptr;
    if (!p_t64) {
        p_t64 = sym_addr(g_t64);
        p_h   = sym_addr(g_h);
        p_gat = sym_addr(g_gat);
    }

    const int B = 256;

    // ---- CSR build (gemm1 slotted at launch index 3 for profiling) ----
    k_prep<<<cdiv(NN, B), B>>>(ei);
    k_convert<<<cdiv(EE, B), B>>>(ei);
    k_scan1<<<SCAN_B, B>>>();
    k_gemm_n64<FIN><<<cdiv(NN, 32), B>>>(x, W1, p_t64);   // index 3 (profiled)
    k_scan2<<<1, B>>>();
    k_scan3<<<cdiv(NN, B), B>>>();
    k_scatter<<<cdiv(EE, B), B>>>();

    // ---- GCN layer 1 ----
    k_gcn_csr<<<cdiv(NN, 8), B>>>(p_t64, b1, p_h);

    // ---- GCN layer 2 ----
    k_gemm_n64<HH><<<cdiv(NN, 32), B>>>(p_h, W2, p_t64);
    k_gcn_csr<<<cdiv(NN, 8), B>>>(p_t64, b2, p_h);

    // ---- GAT ----
    k_gemm_gat<<<cdiv(NN, 32), B>>>(p_h, Wg, att_src, att_dst);
    k_gat_csr<<<cdiv(NN, 8), B>>>(bg, p_gat);

    // ---- FF head (fused Wf1+relu+Wf2) ----
    k_gemm_head<<<cdiv(NN, 32), B>>>(p_gat, Wf1, bf1, Wf2, bf2, out);

    (void)in_sizes; (void)n_in; (void)out_size;
}

// round 7
// speedup vs baseline: 3.7600x; 1.1225x over previous
#include <cuda_runtime.h>
#include <cuda_fp16.h>
#include <math.h>

#define NN   50000
#define EE   800000
#define FIN  256
#define HH   64
#define NHH  4
#define GDIM 256   // NH*H
#define SCAN_B 196 // ceil(50000/256)

// ---------------- device scratch (static, allowed) ----------------
__device__ int      g_flag;
__device__ int      g_src[EE];
__device__ int      g_dst[EE];
__device__ int      g_cnt[NN];
__device__ int      g_row[NN];
__device__ int      g_cursor[NN];
__device__ int      g_bsum[SCAN_B];
__device__ int      g_csr[EE];
__device__ float    g_wn[EE];        // dinv[src] per CSR slot
__device__ float    g_dinv[NN];
__device__ float    g_t64[(size_t)NN * HH];
__device__ float    g_h[(size_t)NN * HH];
__device__ __align__(16) __half g_hph[(size_t)NN * GDIM];
__device__ float    g_gat[(size_t)NN * GDIM];
__device__ float    g_as[NN * NHH];
__device__ float    g_ad[NN * NHH];

__device__ __forceinline__ void fma4(float* a, float x, float4 w) {
    a[0] = fmaf(x, w.x, a[0]);
    a[1] = fmaf(x, w.y, a[1]);
    a[2] = fmaf(x, w.z, a[2]);
    a[3] = fmaf(x, w.w, a[3]);
}

// ---------------- edge prep ----------------
__global__ void k_prep(const int* __restrict__ ei32) {
    int i = blockIdx.x * 256 + threadIdx.x;
    if (i < NN) g_cnt[i] = 0;
    if (blockIdx.x == 0) {
        __shared__ int bad;
        if (threadIdx.x == 0) bad = 0;
        __syncthreads();
        for (int t = threadIdx.x; t < 4096; t += 256)
            if (ei32[2 * t + 1] != 0) bad = 1;
        __syncthreads();
        if (threadIdx.x == 0) g_flag = bad ? 0 : 1;
    }
}

__global__ void k_convert(const int* __restrict__ p) {
    int i = blockIdx.x * blockDim.x + threadIdx.x;
    if (i >= EE) return;
    int s, d;
    if (g_flag) { s = p[2 * i]; d = p[2 * (EE + i)]; }
    else        { s = p[i];     d = p[EE + i]; }
    g_src[i] = s;
    g_dst[i] = d;
    atomicAdd(&g_cnt[d], 1);
}

// ---------------- 2-level exclusive scan of g_cnt ----------------
__global__ void k_scan1() {
    __shared__ int sm[256];
    int tid = threadIdx.x;
    int i = blockIdx.x * 256 + tid;
    int v = (i < NN) ? g_cnt[i] : 0;
    sm[tid] = v;
    __syncthreads();
    for (int o = 1; o < 256; o <<= 1) {
        int t = (tid >= o) ? sm[tid - o] : 0;
        __syncthreads();
        sm[tid] += t;
        __syncthreads();
    }
    if (i < NN) g_row[i] = sm[tid] - v;
    if (tid == 255) g_bsum[blockIdx.x] = sm[255];
}

__global__ void k_scan2() {
    __shared__ int sm[256];
    int tid = threadIdx.x;
    int v = (tid < SCAN_B) ? g_bsum[tid] : 0;
    sm[tid] = v;
    __syncthreads();
    for (int o = 1; o < 256; o <<= 1) {
        int t = (tid >= o) ? sm[tid - o] : 0;
        __syncthreads();
        sm[tid] += t;
        __syncthreads();
    }
    if (tid < SCAN_B) g_bsum[tid] = sm[tid] - v;
}

__global__ void k_scan3() {
    int i = blockIdx.x * blockDim.x + threadIdx.x;
    if (i >= NN) return;
    int r = g_row[i] + g_bsum[i >> 8];
    g_row[i] = r;
    g_cursor[i] = r;
    g_dinv[i] = rsqrtf((float)(g_cnt[i] + 1));
}

__global__ void k_scatter() {
    int i = blockIdx.x * blockDim.x + threadIdx.x;
    if (i >= EE) return;
    int d = g_dst[i];
    int s = g_src[i];
    int pos = atomicAdd(&g_cursor[d], 1);
    g_csr[pos] = s;
    g_wn[pos]  = g_dinv[s];
}

// ---------------- GEMM (DOUT=64): k-major x tile, 4 nodes x 4 cols ------
// block = 64 nodes, 256 threads. jg = tid&15 -> cols jg*4..+3,
// tg = tid>>4 -> nodes tg*4..+3.
template <int DIN>
__global__ __launch_bounds__(256) void k_gemm_n64(const float* __restrict__ X,
                                                  const float* __restrict__ W,
                                                  float* __restrict__ Y) {
    __shared__ float xsT[64][68];   // [k][node], pad 68 (x4 aligned)
    __shared__ float ws[64][64];    // [k][col]
    int jg = threadIdx.x & 15;
    int tg = threadIdx.x >> 4;
    int n0 = blockIdx.x * 64;
    float acc[4][4] = {};
    for (int kt = 0; kt < DIN; kt += 64) {
        __syncthreads();
        for (int idx = threadIdx.x; idx < 64 * 64; idx += 256) {
            int r = idx >> 6, c = idx & 63;
            int n = n0 + r;
            xsT[c][r] = (n < NN) ? X[(size_t)n * DIN + kt + c] : 0.f;
            ws[r][c]  = W[(size_t)(kt + r) * 64 + c];
        }
        __syncthreads();
#pragma unroll 16
        for (int k = 0; k < 64; k++) {
            float4 w4 = *(const float4*)&ws[k][jg * 4];
            float4 xv = *(const float4*)&xsT[k][tg * 4];
            fma4(acc[0], xv.x, w4);
            fma4(acc[1], xv.y, w4);
            fma4(acc[2], xv.z, w4);
            fma4(acc[3], xv.w, w4);
        }
    }
#pragma unroll
    for (int tt = 0; tt < 4; tt++) {
        int n = n0 + tg * 4 + tt;
        if (n < NN)
            *(float4*)&Y[(size_t)n * 64 + jg * 4] =
                make_float4(acc[tt][0], acc[tt][1], acc[tt][2], acc[tt][3]);
    }
}

// ---------------- Wg GEMM (64->256) + att epilogue + fp16 store ----------
// block = 32 nodes. jg = tid&63 -> cols jg*4..+3, tg = tid>>6 -> nodes tg*8..+7.
__global__ __launch_bounds__(256) void k_gemm_gat(const float* __restrict__ X,
                                                  const float* __restrict__ W,
                                                  const float* __restrict__ att_src,
                                                  const float* __restrict__ att_dst) {
    __shared__ float xsT[64][36];   // [k][node], full X tile
    __shared__ float ws[32][256];   // [k][col] staged
    int jg = threadIdx.x & 63;
    int tg = threadIdx.x >> 6;
    int lane = threadIdx.x & 31;
    int n0 = blockIdx.x * 32;
    for (int idx = threadIdx.x; idx < 32 * 64; idx += 256) {
        int r = idx >> 6, c = idx & 63;
        int n = n0 + r;
        xsT[c][r] = (n < NN) ? X[(size_t)n * 64 + c] : 0.f;
    }
    float acc[8][4] = {};
    for (int kt = 0; kt < 64; kt += 32) {
        __syncthreads();
        for (int idx = threadIdx.x; idx < 32 * 256; idx += 256) {
            int r = idx >> 8, c = idx & 255;
            ws[r][c] = W[(size_t)(kt + r) * 256 + c];
        }
        __syncthreads();
#pragma unroll 8
        for (int k = 0; k < 32; k++) {
            float4 w4 = *(const float4*)&ws[k][jg * 4];
            float4 x0 = *(const float4*)&xsT[kt + k][tg * 8];
            float4 x1 = *(const float4*)&xsT[kt + k][tg * 8 + 4];
            fma4(acc[0], x0.x, w4);
            fma4(acc[1], x0.y, w4);
            fma4(acc[2], x0.z, w4);
            fma4(acc[3], x0.w, w4);
            fma4(acc[4], x1.x, w4);
            fma4(acc[5], x1.y, w4);
            fma4(acc[6], x1.z, w4);
            fma4(acc[7], x1.w, w4);
        }
    }
    // ---- attention-logit epilogue (exact fp32) ----
    int j0 = jg * 4;
    int head = jg >> 4;          // 16 jg groups (64 cols) per head
    float4 asw = *(const float4*)&att_src[j0];
    float4 adw = *(const float4*)&att_dst[j0];
#pragma unroll
    for (int tt = 0; tt < 8; tt++) {
        float vs = acc[tt][0] * asw.x + acc[tt][1] * asw.y +
                   acc[tt][2] * asw.z + acc[tt][3] * asw.w;
        float vd = acc[tt][0] * adw.x + acc[tt][1] * adw.y +
                   acc[tt][2] * adw.z + acc[tt][3] * adw.w;
        for (int o = 8; o; o >>= 1) {       // reduce within 16-lane head group
            vs += __shfl_xor_sync(0xffffffffu, vs, o);
            vd += __shfl_xor_sync(0xffffffffu, vd, o);
        }
        if ((lane & 15) == 0) {
            int n = n0 + tg * 8 + tt;
            if (n < NN) {
                g_as[n * 4 + head] = vs;
                g_ad[n * 4 + head] = vd;
            }
        }
    }
    // ---- fp16 hp store ----
#pragma unroll
    for (int tt = 0; tt < 8; tt++) {
        int n = n0 + tg * 8 + tt;
        if (n < NN) {
            union { __half2 h2[2]; uint2 u; } pk;
            pk.h2[0] = __floats2half2_rn(acc[tt][0], acc[tt][1]);
            pk.h2[1] = __floats2half2_rn(acc[tt][2], acc[tt][3]);
            *(uint2*)(g_hph + (size_t)n * GDIM + j0) = pk.u;
        }
    }
}

// ---------------- head GEMM (256->64) + relu + Wf2 dot -> out ------------
__global__ __launch_bounds__(256) void k_gemm_head(const float* __restrict__ X,
                                                   const float* __restrict__ W,
                                                   const float* __restrict__ bf1,
                                                   const float* __restrict__ wf2,
                                                   const float* __restrict__ bf2,
                                                   float* __restrict__ out) {
    __shared__ float xsT[64][68];
    __shared__ float ws[64][64];
    int jg = threadIdx.x & 15;
    int tg = threadIdx.x >> 4;
    int lane = threadIdx.x & 31;
    int n0 = blockIdx.x * 64;
    float acc[4][4] = {};
    for (int kt = 0; kt < 256; kt += 64) {
        __syncthreads();
        for (int idx = threadIdx.x; idx < 64 * 64; idx += 256) {
            int r = idx >> 6, c = idx & 63;
            int n = n0 + r;
            xsT[c][r] = (n < NN) ? X[(size_t)n * 256 + kt + c] : 0.f;
            ws[r][c]  = W[(size_t)(kt + r) * 64 + c];
        }
        __syncthreads();
#pragma unroll 16
        for (int k = 0; k < 64; k++) {
            float4 w4 = *(const float4*)&ws[k][jg * 4];
            float4 xv = *(const float4*)&xsT[k][tg * 4];
            fma4(acc[0], xv.x, w4);
            fma4(acc[1], xv.y, w4);
            fma4(acc[2], xv.z, w4);
            fma4(acc[3], xv.w, w4);
        }
    }
    int j0 = jg * 4;
    float4 b4 = *(const float4*)&bf1[j0];
    float4 w2 = *(const float4*)&wf2[j0];
#pragma unroll
    for (int tt = 0; tt < 4; tt++) {
        float v = fmaxf(acc[tt][0] + b4.x, 0.f) * w2.x +
                  fmaxf(acc[tt][1] + b4.y, 0.f) * w2.y +
                  fmaxf(acc[tt][2] + b4.z, 0.f) * w2.z +
                  fmaxf(acc[tt][3] + b4.w, 0.f) * w2.w;
        for (int o = 8; o; o >>= 1)
            v += __shfl_xor_sync(0xffffffffu, v, o);
        if ((lane & 15) == 0) {
            int n = n0 + tg * 4 + tt;
            if (n < NN) out[n] = v + bf2[0];
        }
    }
}

// ---------------- GCN aggregation (CSR, warp per node) -------------------
__global__ __launch_bounds__(256) void k_gcn_csr(const float* __restrict__ hin,
                                                 const float* __restrict__ b,
                                                 float* __restrict__ out) {
    int wid = threadIdx.x >> 5, lane = threadIdx.x & 31;
    int d = blockIdx.x * 8 + wid;
    if (d >= NN) return;
    int row0 = g_row[d];
    int row1 = row0 + g_cnt[d];
    float dd = g_dinv[d];
    float ax = 0.f, ay = 0.f;
    for (int base = row0; base < row1; base += 32) {
        int e = base + lane;
        int   sl = 0;
        float nl = 0.f;
        if (e < row1) { sl = g_csr[e]; nl = g_wn[e]; }
        int m = min(32, row1 - base);
        for (int i = 0; i < m; i++) {
            int   s    = __shfl_sync(0xffffffffu, sl, i);
            float norm = __shfl_sync(0xffffffffu, nl, i) * dd;
            float2 v = ((const float2*)(hin + (size_t)s * HH))[lane];
            ax = fmaf(v.x, norm, ax);
            ay = fmaf(v.y, norm, ay);
        }
    }
    {   // self loop
        float2 v = ((const float2*)(hin + (size_t)d * HH))[lane];
        float n2 = dd * dd;
        ax = fmaf(v.x, n2, ax);
        ay = fmaf(v.y, n2, ay);
    }
    float2 bb = ((const float2*)b)[lane];
    float2 o;
    o.x = fmaxf(ax + bb.x, 0.f);
    o.y = fmaxf(ay + bb.y, 0.f);
    ((float2*)(out + (size_t)d * HH))[lane] = o;
}

__device__ __forceinline__ float lrelu(float a) {
    return a > 0.f ? a : 0.2f * a;
}
__device__ __forceinline__ float sel4(int h, float a, float b, float c, float d) {
    return h == 0 ? a : (h == 1 ? b : (h == 2 ? c : d));
}

// ---------------- fused GAT (CSR, warp per node, fp16 gather) -------------
__global__ __launch_bounds__(256) void k_gat_csr(const float* __restrict__ bg,
                                                 float* __restrict__ outg) {
    __shared__ int   ssm[8][32];
    __shared__ float wsm[8][32][4];
    int wid = threadIdx.x >> 5, lane = threadIdx.x & 31;
    int d = blockIdx.x * 8 + wid;
    if (d >= NN) return;
    int row0 = g_row[d];
    int row1 = row0 + g_cnt[d];
    int head = lane >> 3;               // 8 dims/lane -> 8 lanes/head

    float ad0 = g_ad[d * 4 + 0], ad1 = g_ad[d * 4 + 1];
    float ad2 = g_ad[d * 4 + 2], ad3 = g_ad[d * 4 + 3];

    // ---- pass 1: per-head max (incl self) ----
    float m0 = -INFINITY, m1 = -INFINITY, m2 = -INFINITY, m3 = -INFINITY;
    for (int e = row0 + lane; e < row1; e += 32) {
        int s = g_csr[e];
        const float* as = g_as + s * 4;
        m0 = fmaxf(m0, lrelu(as[0] + ad0));
        m1 = fmaxf(m1, lrelu(as[1] + ad1));
        m2 = fmaxf(m2, lrelu(as[2] + ad2));
        m3 = fmaxf(m3, lrelu(as[3] + ad3));
    }
    {
        const float* as = g_as + d * 4;
        m0 = fmaxf(m0, lrelu(as[0] + ad0));
        m1 = fmaxf(m1, lrelu(as[1] + ad1));
        m2 = fmaxf(m2, lrelu(as[2] + ad2));
        m3 = fmaxf(m3, lrelu(as[3] + ad3));
    }
    for (int o = 16; o; o >>= 1) {
        m0 = fmaxf(m0, __shfl_xor_sync(0xffffffffu, m0, o));
        m1 = fmaxf(m1, __shfl_xor_sync(0xffffffffu, m1, o));
        m2 = fmaxf(m2, __shfl_xor_sync(0xffffffffu, m2, o));
        m3 = fmaxf(m3, __shfl_xor_sync(0xffffffffu, m3, o));
    }

    // ---- pass 2: exp weights + weighted fp16 gather ----
    float a0 = 0.f, a1 = 0.f, a2 = 0.f, a3 = 0.f;
    float a4 = 0.f, a5 = 0.f, a6 = 0.f, a7 = 0.f;
    float dn0 = 0.f, dn1 = 0.f, dn2 = 0.f, dn3 = 0.f;

    for (int base = row0; base < row1; base += 32) {
        int e = base + lane;
        float w0 = 0.f, w1 = 0.f, w2 = 0.f, w3 = 0.f;
        if (e < row1) {
            int s = g_csr[e];
            ssm[wid][lane] = s;
            const float* as = g_as + s * 4;
            w0 = __expf(lrelu(as[0] + ad0) - m0);
            w1 = __expf(lrelu(as[1] + ad1) - m1);
            w2 = __expf(lrelu(as[2] + ad2) - m2);
            w3 = __expf(lrelu(as[3] + ad3) - m3);
            wsm[wid][lane][0] = w0;
            wsm[wid][lane][1] = w1;
            wsm[wid][lane][2] = w2;
            wsm[wid][lane][3] = w3;
        }
        dn0 += w0; dn1 += w1; dn2 += w2; dn3 += w3;
        __syncwarp();
        int m = min(32, row1 - base);
        for (int i = 0; i < m; i++) {
            int   s  = ssm[wid][i];
            float wt = wsm[wid][i][head];
            uint4 p = *(const uint4*)(g_hph + (size_t)s * GDIM + lane * 8);
            float2 f0 = __half22float2(*(__half2*)&p.x);
            float2 f1 = __half22float2(*(__half2*)&p.y);
            float2 f2 = __half22float2(*(__half2*)&p.z);
            float2 f3 = __half22float2(*(__half2*)&p.w);
            a0 = fmaf(f0.x, wt, a0); a1 = fmaf(f0.y, wt, a1);
            a2 = fmaf(f1.x, wt, a2); a3 = fmaf(f1.y, wt, a3);
            a4 = fmaf(f2.x, wt, a4); a5 = fmaf(f2.y, wt, a5);
            a6 = fmaf(f3.x, wt, a6); a7 = fmaf(f3.y, wt, a7);
        }
        __syncwarp();
    }
    for (int o = 16; o; o >>= 1) {
        dn0 += __shfl_xor_sync(0xffffffffu, dn0, o);
        dn1 += __shfl_xor_sync(0xffffffffu, dn1, o);
        dn2 += __shfl_xor_sync(0xffffffffu, dn2, o);
        dn3 += __shfl_xor_sync(0xffffffffu, dn3, o);
    }
    float mh  = sel4(head, m0, m1, m2, m3);
    float adh = sel4(head, ad0, ad1, ad2, ad3);
    float dnh = sel4(head, dn0, dn1, dn2, dn3);

    // self loop
    float wslf = __expf(lrelu(g_as[d * 4 + head] + adh) - mh);
    dnh += wslf;
    {
        uint4 p = *(const uint4*)(g_hph + (size_t)d * GDIM + lane * 8);
        float2 f0 = __half22float2(*(__half2*)&p.x);
        float2 f1 = __half22float2(*(__half2*)&p.y);
        float2 f2 = __half22float2(*(__half2*)&p.z);
        float2 f3 = __half22float2(*(__half2*)&p.w);
        a0 = fmaf(f0.x, wslf, a0); a1 = fmaf(f0.y, wslf, a1);
        a2 = fmaf(f1.x, wslf, a2); a3 = fmaf(f1.y, wslf, a3);
        a4 = fmaf(f2.x, wslf, a4); a5 = fmaf(f2.y, wslf, a5);
        a6 = fmaf(f3.x, wslf, a6); a7 = fmaf(f3.y, wslf, a7);
    }
    float inv = 1.f / dnh;
    const float4* bg4 = (const float4*)(bg + lane * 8);
    float4 b0 = bg4[0], b1 = bg4[1];
    float4 o0 = make_float4(a0 * inv + b0.x, a1 * inv + b0.y,
                            a2 * inv + b0.z, a3 * inv + b0.w);
    float4 o1 = make_float4(a4 * inv + b1.x, a5 * inv + b1.y,
                            a6 * inv + b1.z, a7 * inv + b1.w);
    float4* out4 = (float4*)(outg + (size_t)d * GDIM + lane * 8);
    out4[0] = o0;
    out4[1] = o1;
}

static inline int cdiv(long long a, int b) { return (int)((a + b - 1) / b); }

static float* sym_addr(const void* sym) {
    void* p = nullptr;
    cudaGetSymbolAddress(&p, sym);
    return (float*)p;
}

extern "C" void kernel_launch(void* const* d_in, const int* in_sizes, int n_in,
                              void* d_out, int out_size) {
    const float* x       = (const float*)d_in[0];
    const int*   ei      = (const int*)  d_in[1];
    const float* W1      = (const float*)d_in[2];
    const float* b1      = (const float*)d_in[3];
    const float* W2      = (const float*)d_in[4];
    const float* b2      = (const float*)d_in[5];
    const float* Wg      = (const float*)d_in[6];
    const float* att_src = (const float*)d_in[7];
    const float* att_dst = (const float*)d_in[8];
    const float* bg      = (const float*)d_in[9];
    const float* Wf1     = (const float*)d_in[10];
    const float* bf1     = (const float*)d_in[11];
    const float* Wf2     = (const float*)d_in[12];
    const float* bf2     = (const float*)d_in[13];
    float*       out     = (float*)d_out;

    static float* p_t64 = nullptr;
    static float* p_h   = nullptr;
    static float* p_gat = nullptr;
    if (!p_t64) {
        p_t64 = sym_addr(g_t64);
        p_h   = sym_addr(g_h);
        p_gat = sym_addr(g_gat);
    }

    const int B = 256;

    // ---- CSR build (gemm1 slotted at launch index 3 for profiling) ----
    k_prep<<<cdiv(NN, B), B>>>(ei);
    k_convert<<<cdiv(EE, B), B>>>(ei);
    k_scan1<<<SCAN_B, B>>>();
    k_gemm_n64<FIN><<<cdiv(NN, 64), B>>>(x, W1, p_t64);   // index 3 (profiled)
    k_scan2<<<1, B>>>();
    k_scan3<<<cdiv(NN, B), B>>>();
    k_scatter<<<cdiv(EE, B), B>>>();

    // ---- GCN layer 1 ----
    k_gcn_csr<<<cdiv(NN, 8), B>>>(p_t64, b1, p_h);

    // ---- GCN layer 2 ----
    k_gemm_n64<HH><<<cdiv(NN, 64), B>>>(p_h, W2, p_t64);
    k_gcn_csr<<<cdiv(NN, 8), B>>>(p_t64, b2, p_h);

    // ---- GAT ----
    k_gemm_gat<<<cdiv(NN, 32), B>>>(p_h, Wg, att_src, att_dst);
    k_gat_csr<<<cdiv(NN, 8), B>>>(bg, p_gat);

    // ---- FF head (fused Wf1+relu+Wf2) ----
    k_gemm_head<<<cdiv(NN, 64), B>>>(p_gat, Wf1, bf1, Wf2, bf2, out);

    (void)in_sizes; (void)n_in; (void)out_size;
}

// round 8
// speedup vs baseline: 3.7859x; 1.0069x over previous
#include <cuda_runtime.h>
#include <cuda_fp16.h>
#include <math.h>

#define NN   50000
#define EE   800000
#define FIN  256
#define HH   64
#define NHH  4
#define GDIM 256   // NH*H
#define SCAN_B 196 // ceil(50000/256)

// ---------------- device scratch (static, allowed) ----------------
__device__ int      g_flag;
__device__ int      g_src[EE];
__device__ int      g_dst[EE];
__device__ int      g_cnt[NN];
__device__ int      g_row[NN];
__device__ int      g_cursor[NN];
__device__ int      g_bsum[SCAN_B];
__device__ int      g_csr[EE];
__device__ float    g_wn[EE];        // dinv[src] per CSR slot
__device__ float    g_dinv[NN];
__device__ __align__(16) __half g_t64[(size_t)NN * HH];   // fp16 pre-agg features
__device__ float    g_h[(size_t)NN * HH];
__device__ __align__(16) __half g_hph[(size_t)NN * GDIM];
__device__ float    g_gat[(size_t)NN * GDIM];
__device__ float    g_as[NN * NHH];
__device__ float    g_ad[NN * NHH];

__device__ __forceinline__ void fma4(float* a, float x, float4 w) {
    a[0] = fmaf(x, w.x, a[0]);
    a[1] = fmaf(x, w.y, a[1]);
    a[2] = fmaf(x, w.z, a[2]);
    a[3] = fmaf(x, w.w, a[3]);
}

// ---------------- edge prep ----------------
__global__ void k_prep(const int* __restrict__ ei32) {
    int i = blockIdx.x * 256 + threadIdx.x;
    if (i < NN) g_cnt[i] = 0;
    if (blockIdx.x == 0) {
        __shared__ int bad;
        if (threadIdx.x == 0) bad = 0;
        __syncthreads();
        for (int t = threadIdx.x; t < 4096; t += 256)
            if (ei32[2 * t + 1] != 0) bad = 1;
        __syncthreads();
        if (threadIdx.x == 0) g_flag = bad ? 0 : 1;
    }
}

__global__ void k_convert(const int* __restrict__ p) {
    int i = blockIdx.x * blockDim.x + threadIdx.x;
    if (i >= EE) return;
    int s, d;
    if (g_flag) { s = p[2 * i]; d = p[2 * (EE + i)]; }
    else        { s = p[i];     d = p[EE + i]; }
    g_src[i] = s;
    g_dst[i] = d;
    atomicAdd(&g_cnt[d], 1);
}

// ---------------- 2-level exclusive scan of g_cnt ----------------
__global__ void k_scan1() {
    __shared__ int sm[256];
    int tid = threadIdx.x;
    int i = blockIdx.x * 256 + tid;
    int v = (i < NN) ? g_cnt[i] : 0;
    sm[tid] = v;
    __syncthreads();
    for (int o = 1; o < 256; o <<= 1) {
        int t = (tid >= o) ? sm[tid - o] : 0;
        __syncthreads();
        sm[tid] += t;
        __syncthreads();
    }
    if (i < NN) g_row[i] = sm[tid] - v;
    if (tid == 255) g_bsum[blockIdx.x] = sm[255];
}

__global__ void k_scan2() {
    __shared__ int sm[256];
    int tid = threadIdx.x;
    int v = (tid < SCAN_B) ? g_bsum[tid] : 0;
    sm[tid] = v;
    __syncthreads();
    for (int o = 1; o < 256; o <<= 1) {
        int t = (tid >= o) ? sm[tid - o] : 0;
        __syncthreads();
        sm[tid] += t;
        __syncthreads();
    }
    if (tid < SCAN_B) g_bsum[tid] = sm[tid] - v;
}

__global__ void k_scan3() {
    int i = blockIdx.x * blockDim.x + threadIdx.x;
    if (i >= NN) return;
    int r = g_row[i] + g_bsum[i >> 8];
    g_row[i] = r;
    g_cursor[i] = r;
    g_dinv[i] = rsqrtf((float)(g_cnt[i] + 1));
}

__global__ void k_scatter() {
    int i = blockIdx.x * blockDim.x + threadIdx.x;
    if (i >= EE) return;
    int d = g_dst[i];
    int s = g_src[i];
    int pos = atomicAdd(&g_cursor[d], 1);
    g_csr[pos] = s;
    g_wn[pos]  = g_dinv[s];
}

// ---------------- GEMM (DOUT=64): k-major x tile, 4 nodes x 4 cols ------
// Writes fp16 output (feeds the GCN gather).
template <int DIN>
__global__ __launch_bounds__(256) void k_gemm_n64(const float* __restrict__ X,
                                                  const float* __restrict__ W,
                                                  __half* __restrict__ Y) {
    __shared__ float xsT[64][68];   // [k][node]
    __shared__ float ws[64][64];    // [k][col]
    int jg = threadIdx.x & 15;
    int tg = threadIdx.x >> 4;
    int n0 = blockIdx.x * 64;
    float acc[4][4] = {};
    for (int kt = 0; kt < DIN; kt += 64) {
        __syncthreads();
        for (int idx = threadIdx.x; idx < 64 * 64; idx += 256) {
            int r = idx >> 6, c = idx & 63;
            int n = n0 + r;
            xsT[c][r] = (n < NN) ? X[(size_t)n * DIN + kt + c] : 0.f;
            ws[r][c]  = W[(size_t)(kt + r) * 64 + c];
        }
        __syncthreads();
#pragma unroll 16
        for (int k = 0; k < 64; k++) {
            float4 w4 = *(const float4*)&ws[k][jg * 4];
            float4 xv = *(const float4*)&xsT[k][tg * 4];
            fma4(acc[0], xv.x, w4);
            fma4(acc[1], xv.y, w4);
            fma4(acc[2], xv.z, w4);
            fma4(acc[3], xv.w, w4);
        }
    }
#pragma unroll
    for (int tt = 0; tt < 4; tt++) {
        int n = n0 + tg * 4 + tt;
        if (n < NN) {
            union { __half2 h2[2]; uint2 u; } pk;
            pk.h2[0] = __floats2half2_rn(acc[tt][0], acc[tt][1]);
            pk.h2[1] = __floats2half2_rn(acc[tt][2], acc[tt][3]);
            *(uint2*)(Y + (size_t)n * 64 + jg * 4) = pk.u;
        }
    }
}

// ---------------- Wg GEMM (64->256) + att epilogue + fp16 store ----------
__global__ __launch_bounds__(256) void k_gemm_gat(const float* __restrict__ X,
                                                  const float* __restrict__ W,
                                                  const float* __restrict__ att_src,
                                                  const float* __restrict__ att_dst) {
    __shared__ float xsT[64][36];   // [k][node], full X tile
    __shared__ float ws[32][256];   // [k][col] staged
    int jg = threadIdx.x & 63;
    int tg = threadIdx.x >> 6;
    int lane = threadIdx.x & 31;
    int n0 = blockIdx.x * 32;
    for (int idx = threadIdx.x; idx < 32 * 64; idx += 256) {
        int r = idx >> 6, c = idx & 63;
        int n = n0 + r;
        xsT[c][r] = (n < NN) ? X[(size_t)n * 64 + c] : 0.f;
    }
    float acc[8][4] = {};
    for (int kt = 0; kt < 64; kt += 32) {
        __syncthreads();
        for (int idx = threadIdx.x; idx < 32 * 256; idx += 256) {
            int r = idx >> 8, c = idx & 255;
            ws[r][c] = W[(size_t)(kt + r) * 256 + c];
        }
        __syncthreads();
#pragma unroll 8
        for (int k = 0; k < 32; k++) {
            float4 w4 = *(const float4*)&ws[k][jg * 4];
            float4 x0 = *(const float4*)&xsT[kt + k][tg * 8];
            float4 x1 = *(const float4*)&xsT[kt + k][tg * 8 + 4];
            fma4(acc[0], x0.x, w4);
            fma4(acc[1], x0.y, w4);
            fma4(acc[2], x0.z, w4);
            fma4(acc[3], x0.w, w4);
            fma4(acc[4], x1.x, w4);
            fma4(acc[5], x1.y, w4);
            fma4(acc[6], x1.z, w4);
            fma4(acc[7], x1.w, w4);
        }
    }
    // ---- attention-logit epilogue (exact fp32) ----
    int j0 = jg * 4;
    int head = jg >> 4;          // 16 jg groups (64 cols) per head
    float4 asw = *(const float4*)&att_src[j0];
    float4 adw = *(const float4*)&att_dst[j0];
#pragma unroll
    for (int tt = 0; tt < 8; tt++) {
        float vs = acc[tt][0] * asw.x + acc[tt][1] * asw.y +
                   acc[tt][2] * asw.z + acc[tt][3] * asw.w;
        float vd = acc[tt][0] * adw.x + acc[tt][1] * adw.y +
                   acc[tt][2] * adw.z + acc[tt][3] * adw.w;
        for (int o = 8; o; o >>= 1) {       // reduce within 16-lane head group
            vs += __shfl_xor_sync(0xffffffffu, vs, o);
            vd += __shfl_xor_sync(0xffffffffu, vd, o);
        }
        if ((lane & 15) == 0) {
            int n = n0 + tg * 8 + tt;
            if (n < NN) {
                g_as[n * 4 + head] = vs;
                g_ad[n * 4 + head] = vd;
            }
        }
    }
    // ---- fp16 hp store ----
#pragma unroll
    for (int tt = 0; tt < 8; tt++) {
        int n = n0 + tg * 8 + tt;
        if (n < NN) {
            union { __half2 h2[2]; uint2 u; } pk;
            pk.h2[0] = __floats2half2_rn(acc[tt][0], acc[tt][1]);
            pk.h2[1] = __floats2half2_rn(acc[tt][2], acc[tt][3]);
            *(uint2*)(g_hph + (size_t)n * GDIM + j0) = pk.u;
        }
    }
}

// ---------------- head GEMM (256->64) + relu + Wf2 dot -> out ------------
__global__ __launch_bounds__(256) void k_gemm_head(const float* __restrict__ X,
                                                   const float* __restrict__ W,
                                                   const float* __restrict__ bf1,
                                                   const float* __restrict__ wf2,
                                                   const float* __restrict__ bf2,
                                                   float* __restrict__ out) {
    __shared__ float xsT[64][68];
    __shared__ float ws[64][64];
    int jg = threadIdx.x & 15;
    int tg = threadIdx.x >> 4;
    int lane = threadIdx.x & 31;
    int n0 = blockIdx.x * 64;
    float acc[4][4] = {};
    for (int kt = 0; kt < 256; kt += 64) {
        __syncthreads();
        for (int idx = threadIdx.x; idx < 64 * 64; idx += 256) {
            int r = idx >> 6, c = idx & 63;
            int n = n0 + r;
            xsT[c][r] = (n < NN) ? X[(size_t)n * 256 + kt + c] : 0.f;
            ws[r][c]  = W[(size_t)(kt + r) * 64 + c];
        }
        __syncthreads();
#pragma unroll 16
        for (int k = 0; k < 64; k++) {
            float4 w4 = *(const float4*)&ws[k][jg * 4];
            float4 xv = *(const float4*)&xsT[k][tg * 4];
            fma4(acc[0], xv.x, w4);
            fma4(acc[1], xv.y, w4);
            fma4(acc[2], xv.z, w4);
            fma4(acc[3], xv.w, w4);
        }
    }
    int j0 = jg * 4;
    float4 b4 = *(const float4*)&bf1[j0];
    float4 w2 = *(const float4*)&wf2[j0];
#pragma unroll
    for (int tt = 0; tt < 4; tt++) {
        float v = fmaxf(acc[tt][0] + b4.x, 0.f) * w2.x +
                  fmaxf(acc[tt][1] + b4.y, 0.f) * w2.y +
                  fmaxf(acc[tt][2] + b4.z, 0.f) * w2.z +
                  fmaxf(acc[tt][3] + b4.w, 0.f) * w2.w;
        for (int o = 8; o; o >>= 1)
            v += __shfl_xor_sync(0xffffffffu, v, o);
        if ((lane & 15) == 0) {
            int n = n0 + tg * 4 + tt;
            if (n < NN) out[n] = v + bf2[0];
        }
    }
}

// ---------------- GCN aggregation (CSR, warp per node, fp16 gather) ------
__global__ __launch_bounds__(256) void k_gcn_csr(const __half* __restrict__ hin,
                                                 const float* __restrict__ b,
                                                 float* __restrict__ out) {
    int wid = threadIdx.x >> 5, lane = threadIdx.x & 31;
    int d = blockIdx.x * 8 + wid;
    if (d >= NN) return;
    int row0 = g_row[d];
    int row1 = row0 + g_cnt[d];
    float dd = g_dinv[d];
    float ax = 0.f, ay = 0.f;
    for (int base = row0; base < row1; base += 32) {
        int e = base + lane;
        int   sl = 0;
        float nl = 0.f;
        if (e < row1) { sl = g_csr[e]; nl = g_wn[e]; }
        int m = min(32, row1 - base);
        for (int i = 0; i < m; i++) {
            int   s    = __shfl_sync(0xffffffffu, sl, i);
            float norm = __shfl_sync(0xffffffffu, nl, i) * dd;
            __half2 hv = *(const __half2*)(hin + (size_t)s * HH + 2 * lane);
            float2 v = __half22float2(hv);
            ax = fmaf(v.x, norm, ax);
            ay = fmaf(v.y, norm, ay);
        }
    }
    {   // self loop
        __half2 hv = *(const __half2*)(hin + (size_t)d * HH + 2 * lane);
        float2 v = __half22float2(hv);
        float n2 = dd * dd;
        ax = fmaf(v.x, n2, ax);
        ay = fmaf(v.y, n2, ay);
    }
    float2 bb = ((const float2*)b)[lane];
    float2 o;
    o.x = fmaxf(ax + bb.x, 0.f);
    o.y = fmaxf(ay + bb.y, 0.f);
    ((float2*)(out + (size_t)d * HH))[lane] = o;
}

__device__ __forceinline__ float lrelu(float a) {
    return a > 0.f ? a : 0.2f * a;
}
__device__ __forceinline__ float sel4(int h, float a, float b, float c, float d) {
    return h == 0 ? a : (h == 1 ? b : (h == 2 ? c : d));
}

// ---------------- fused GAT (CSR, warp per node, fp16 gather) -------------
__global__ __launch_bounds__(256) void k_gat_csr(const float* __restrict__ bg,
                                                 float* __restrict__ outg) {
    __shared__ int   ssm[8][32];
    __shared__ float wsm[8][32][4];
    int wid = threadIdx.x >> 5, lane = threadIdx.x & 31;
    int d = blockIdx.x * 8 + wid;
    if (d >= NN) return;
    int row0 = g_row[d];
    int row1 = row0 + g_cnt[d];
    int head = lane >> 3;               // 8 dims/lane -> 8 lanes/head

    float ad0 = g_ad[d * 4 + 0], ad1 = g_ad[d * 4 + 1];
    float ad2 = g_ad[d * 4 + 2], ad3 = g_ad[d * 4 + 3];

    // ---- pass 1: per-head max (incl self) ----
    float m0 = -INFINITY, m1 = -INFINITY, m2 = -INFINITY, m3 = -INFINITY;
    for (int e = row0 + lane; e < row1; e += 32) {
        int s = g_csr[e];
        const float* as = g_as + s * 4;
        m0 = fmaxf(m0, lrelu(as[0] + ad0));
        m1 = fmaxf(m1, lrelu(as[1] + ad1));
        m2 = fmaxf(m2, lrelu(as[2] + ad2));
        m3 = fmaxf(m3, lrelu(as[3] + ad3));
    }
    {
        const float* as = g_as + d * 4;
        m0 = fmaxf(m0, lrelu(as[0] + ad0));
        m1 = fmaxf(m1, lrelu(as[1] + ad1));
        m2 = fmaxf(m2, lrelu(as[2] + ad2));
        m3 = fmaxf(m3, lrelu(as[3] + ad3));
    }
    for (int o = 16; o; o >>= 1) {
        m0 = fmaxf(m0, __shfl_xor_sync(0xffffffffu, m0, o));
        m1 = fmaxf(m1, __shfl_xor_sync(0xffffffffu, m1, o));
        m2 = fmaxf(m2, __shfl_xor_sync(0xffffffffu, m2, o));
        m3 = fmaxf(m3, __shfl_xor_sync(0xffffffffu, m3, o));
    }

    // ---- pass 2: exp weights + weighted fp16 gather ----
    float a0 = 0.f, a1 = 0.f, a2 = 0.f, a3 = 0.f;
    float a4 = 0.f, a5 = 0.f, a6 = 0.f, a7 = 0.f;
    float dn0 = 0.f, dn1 = 0.f, dn2 = 0.f, dn3 = 0.f;

    for (int base = row0; base < row1; base += 32) {
        int e = base + lane;
        float w0 = 0.f, w1 = 0.f, w2 = 0.f, w3 = 0.f;
        if (e < row1) {
            int s = g_csr[e];
            ssm[wid][lane] = s;
            const float* as = g_as + s * 4;
            w0 = __expf(lrelu(as[0] + ad0) - m0);
            w1 = __expf(lrelu(as[1] + ad1) - m1);
            w2 = __expf(lrelu(as[2] + ad2) - m2);
            w3 = __expf(lrelu(as[3] + ad3) - m3);
            wsm[wid][lane][0] = w0;
            wsm[wid][lane][1] = w1;
            wsm[wid][lane][2] = w2;
            wsm[wid][lane][3] = w3;
        }
        dn0 += w0; dn1 += w1; dn2 += w2; dn3 += w3;
        __syncwarp();
        int m = min(32, row1 - base);
        for (int i = 0; i < m; i++) {
            int   s  = ssm[wid][i];
            float wt = wsm[wid][i][head];
            uint4 p = *(const uint4*)(g_hph + (size_t)s * GDIM + lane * 8);
            float2 f0 = __half22float2(*(__half2*)&p.x);
            float2 f1 = __half22float2(*(__half2*)&p.y);
            float2 f2 = __half22float2(*(__half2*)&p.z);
            float2 f3 = __half22float2(*(__half2*)&p.w);
            a0 = fmaf(f0.x, wt, a0); a1 = fmaf(f0.y, wt, a1);
            a2 = fmaf(f1.x, wt, a2); a3 = fmaf(f1.y, wt, a3);
            a4 = fmaf(f2.x, wt, a4); a5 = fmaf(f2.y, wt, a5);
            a6 = fmaf(f3.x, wt, a6); a7 = fmaf(f3.y, wt, a7);
        }
        __syncwarp();
    }
    for (int o = 16; o; o >>= 1) {
        dn0 += __shfl_xor_sync(0xffffffffu, dn0, o);
        dn1 += __shfl_xor_sync(0xffffffffu, dn1, o);
        dn2 += __shfl_xor_sync(0xffffffffu, dn2, o);
        dn3 += __shfl_xor_sync(0xffffffffu, dn3, o);
    }
    float mh  = sel4(head, m0, m1, m2, m3);
    float adh = sel4(head, ad0, ad1, ad2, ad3);
    float dnh = sel4(head, dn0, dn1, dn2, dn3);

    // self loop
    float wslf = __expf(lrelu(g_as[d * 4 + head] + adh) - mh);
    dnh += wslf;
    {
        uint4 p = *(const uint4*)(g_hph + (size_t)d * GDIM + lane * 8);
        float2 f0 = __half22float2(*(__half2*)&p.x);
        float2 f1 = __half22float2(*(__half2*)&p.y);
        float2 f2 = __half22float2(*(__half2*)&p.z);
        float2 f3 = __half22float2(*(__half2*)&p.w);
        a0 = fmaf(f0.x, wslf, a0); a1 = fmaf(f0.y, wslf, a1);
        a2 = fmaf(f1.x, wslf, a2); a3 = fmaf(f1.y, wslf, a3);
        a4 = fmaf(f2.x, wslf, a4); a5 = fmaf(f2.y, wslf, a5);
        a6 = fmaf(f3.x, wslf, a6); a7 = fmaf(f3.y, wslf, a7);
    }
    float inv = 1.f / dnh;
    const float4* bg4 = (const float4*)(bg + lane * 8);
    float4 b0 = bg4[0], b1 = bg4[1];
    float4 o0 = make_float4(a0 * inv + b0.x, a1 * inv + b0.y,
                            a2 * inv + b0.z, a3 * inv + b0.w);
    float4 o1 = make_float4(a4 * inv + b1.x, a5 * inv + b1.y,
                            a6 * inv + b1.z, a7 * inv + b1.w);
    float4* out4 = (float4*)(outg + (size_t)d * GDIM + lane * 8);
    out4[0] = o0;
    out4[1] = o1;
}

static inline int cdiv(long long a, int b) { return (int)((a + b - 1) / b); }

static void* sym_addr(const void* sym) {
    void* p = nullptr;
    cudaGetSymbolAddress(&p, sym);
    return p;
}

extern "C" void kernel_launch(void* const* d_in, const int* in_sizes, int n_in,
                              void* d_out, int out_size) {
    const float* x       = (const float*)d_in[0];
    const int*   ei      = (const int*)  d_in[1];
    const float* W1      = (const float*)d_in[2];
    const float* b1      = (const float*)d_in[3];
    const float* W2      = (const float*)d_in[4];
    const float* b2      = (const float*)d_in[5];
    const float* Wg      = (const float*)d_in[6];
    const float* att_src = (const float*)d_in[7];
    const float* att_dst = (const float*)d_in[8];
    const float* bg      = (const float*)d_in[9];
    const float* Wf1     = (const float*)d_in[10];
    const float* bf1     = (const float*)d_in[11];
    const float* Wf2     = (const float*)d_in[12];
    const float* bf2     = (const float*)d_in[13];
    float*       out     = (float*)d_out;

    static __half* p_t64 = nullptr;
    static float*  p_h   = nullptr;
    static float*  p_gat = nullptr;
    if (!p_t64) {
        p_t64 = (__half*)sym_addr(g_t64);
        p_h   = (float*) sym_addr(g_h);
        p_gat = (float*) sym_addr(g_gat);
    }

    const int B = 256;

    // ---- CSR build (gemm1 slotted at launch index 3 for profiling) ----
    k_prep<<<cdiv(NN, B), B>>>(ei);
    k_convert<<<cdiv(EE, B), B>>>(ei);
    k_scan1<<<SCAN_B, B>>>();
    k_gemm_n64<FIN><<<cdiv(NN, 64), B>>>(x, W1, p_t64);   // index 3 (profiled)
    k_scan2<<<1, B>>>();
    k_scan3<<<cdiv(NN, B), B>>>();
    k_scatter<<<cdiv(EE, B), B>>>();

    // ---- GCN layer 1 ----
    k_gcn_csr<<<cdiv(NN, 8), B>>>(p_t64, b1, p_h);

    // ---- GCN layer 2 ----
    k_gemm_n64<HH><<<cdiv(NN, 64), B>>>(p_h, W2, p_t64);
    k_gcn_csr<<<cdiv(NN, 8), B>>>(p_t64, b2, p_h);

    // ---- GAT ----
    k_gemm_gat<<<cdiv(NN, 32), B>>>(p_h, Wg, att_src, att_dst);
    k_gat_csr<<<cdiv(NN, 8), B>>>(bg, p_gat);

    // ---- FF head (fused Wf1+relu+Wf2) ----
    k_gemm_head<<<cdiv(NN, 64), B>>>(p_gat, Wf1, bf1, Wf2, bf2, out);

    (void)in_sizes; (void)n_in; (void)out_size;
}